// round 16
// baseline (speedup 1.0000x reference)
#include <cuda_runtime.h>

// x: (B=64, C=128, T=10000) float32, row-major.
#define B_DIM 64
#define C_DIM 128
#define T_DIM 10000
#define T4    2500

// Chunking: 8 chunks of 8 batches (41 MB). Producer (mu of chunk k+1) and
// consumer (norm of chunk k) run CONCURRENTLY in one launch, roles interleaved
// by blockIdx so every wave mixes DRAM-read (mu) with DRAM-write (norm).
#define NCHUNK      8
#define B_PER_CHUNK (B_DIM / NCHUNK)          // 8
#define CHUNK_QUADS (B_PER_CHUNK * T4)        // 20000 float4
#define CHUNK_ROWS  (B_PER_CHUNK * C_DIM)     // 1024

#define THREADS 512

// Step-kernel grid: 128 groups x (8 norm + 5 mu) = 1024 norm + 640 mu CTAs.
#define GRP_NORM 8
#define GRP_MU   5
#define GRP_SZ   (GRP_NORM + GRP_MU)          // 13
#define NGROUPS  128
#define STEP_GRID (NGROUPS * GRP_SZ)          // 1664

// mu geometry (512 threads): 32 quads x 16 groups x 8 channels.
#define MU_QPC  32
#define MU_GPC  16
#define MU_CPG  8
#define MU_JOBS (CHUNK_QUADS / MU_QPC)        // 625 (15 of 640 CTAs idle)

// norm per-thread pipeline.
#define K2_ITERS 5                            // ceil(2500/512)

__device__ float g_mu[B_DIM * T_DIM];         // 2.56 MB, L2-hot

// ---------------------------------------------------------------------------
// mu role: park chunk `chunk` in L2 (evict-normal loads) while computing its
// channel means. Lanes = consecutive quads -> 512B coalesced warp reads.
// ---------------------------------------------------------------------------
__device__ __forceinline__ void mu_body(const float* __restrict__ x,
                                        int chunk, int job) {
    __shared__ float4 part[MU_GPC][MU_QPC];   // 8 KB

    const int ql = threadIdx.x & 31;
    const int g  = threadIdx.x >> 5;          // 0..15
    const int q  = chunk * CHUNK_QUADS + job * MU_QPC + ql;
    const int b  = q / T4;
    const int i4 = q - b * T4;

    const float4* __restrict__ xp =
        reinterpret_cast<const float4*>(x)
        + ((size_t)b * C_DIM + (size_t)g * MU_CPG) * T4 + i4;

    float sx = 0.f, sy = 0.f, sz = 0.f, sw = 0.f;
#pragma unroll
    for (int c = 0; c < MU_CPG; ++c) {
        float4 v = xp[(size_t)c * T4];        // evict-normal: park in L2
        sx += v.x; sy += v.y; sz += v.z; sw += v.w;
    }
    float4 p; p.x = sx; p.y = sy; p.z = sz; p.w = sw;
    part[g][ql] = p;
    __syncthreads();

    if (threadIdx.x < MU_QPC) {
        float4 a = part[0][ql];
#pragma unroll
        for (int gg = 1; gg < MU_GPC; ++gg) {
            float4 t = part[gg][ql];
            a.x += t.x; a.y += t.y; a.z += t.z; a.w += t.w;
        }
        const float inv = 1.0f / (float)C_DIM;
        a.x *= inv; a.y *= inv; a.z *= inv; a.w *= inv;
        reinterpret_cast<float4*>(g_mu)[(size_t)b * T4 + i4] = a;
    }
}

// ---------------------------------------------------------------------------
// norm role: one CTA per (b,c) row of chunk `chunk`. d = x - mu in registers
// across the block reduction. x via __ldcs (demote after L2 hit), mu default.
// out via __stwt: WRITE-THROUGH, no L2 allocation — halves L2 traffic and
// stops the write stream from churning the parked chunk.
// ---------------------------------------------------------------------------
__device__ __forceinline__ void norm_body(const float* __restrict__ x,
                                          float* __restrict__ out,
                                          int chunk, int nrow) {
    __shared__ float red_s[16], red_s2[16];
    __shared__ float s_mean, s_inv;

    const int row = chunk * CHUNK_ROWS + nrow;
    const int b   = row >> 7;

    const float4* __restrict__ xp =
        reinterpret_cast<const float4*>(x) + (size_t)row * T4;
    const float4* __restrict__ mp =
        reinterpret_cast<const float4*>(g_mu) + (size_t)b * T4;

    float4 xv[K2_ITERS], mv[K2_ITERS];
#pragma unroll
    for (int k = 0; k < K2_ITERS; ++k) {
        const int i = threadIdx.x + k * THREADS;
        if (i < T4) {
            xv[k] = __ldcs(xp + i);
            mv[k] = mp[i];
        }
    }

    float s = 0.f, s2 = 0.f;
#pragma unroll
    for (int k = 0; k < K2_ITERS; ++k) {
        const int i = threadIdx.x + k * THREADS;
        if (i < T4) {
            xv[k].x -= mv[k].x; xv[k].y -= mv[k].y;
            xv[k].z -= mv[k].z; xv[k].w -= mv[k].w;
            s  += xv[k].x + xv[k].y + xv[k].z + xv[k].w;
            s2 += xv[k].x * xv[k].x + xv[k].y * xv[k].y
                + xv[k].z * xv[k].z + xv[k].w * xv[k].w;
        }
    }

#pragma unroll
    for (int o = 16; o > 0; o >>= 1) {
        s  += __shfl_down_sync(0xffffffffu, s,  o);
        s2 += __shfl_down_sync(0xffffffffu, s2, o);
    }
    const int wid = threadIdx.x >> 5;
    const int lid = threadIdx.x & 31;
    if (lid == 0) { red_s[wid] = s; red_s2[wid] = s2; }
    __syncthreads();

    if (threadIdx.x < 32) {
        float a  = (lid < 16) ? red_s[lid]  : 0.f;
        float a2 = (lid < 16) ? red_s2[lid] : 0.f;
#pragma unroll
        for (int o = 8; o > 0; o >>= 1) {
            a  += __shfl_down_sync(0xffffffffu, a,  o);
            a2 += __shfl_down_sync(0xffffffffu, a2, o);
        }
        if (lid == 0) {
            const float invT = 1.0f / (float)T_DIM;
            float mean = a * invT;
            float var  = a2 * invT - mean * mean;
            float sd   = sqrtf(fmaxf(var, 0.0f));
            if (sd == 0.0f) sd = 1.0f;
            s_mean = mean;
            s_inv  = 1.0f / sd;
        }
    }
    __syncthreads();

    const float mean = s_mean;
    const float invs = s_inv;
    float4* __restrict__ op = reinterpret_cast<float4*>(out) + (size_t)row * T4;
#pragma unroll
    for (int k = 0; k < K2_ITERS; ++k) {
        const int i = threadIdx.x + k * THREADS;
        if (i < T4) {
            float4 r;
            r.x = (xv[k].x - mean) * invs;
            r.y = (xv[k].y - mean) * invs;
            r.z = (xv[k].z - mean) * invs;
            r.w = (xv[k].w - mean) * invs;
            __stwt(op + i, r);            // write-through: bypass L2 allocation
        }
    }
}

// ---------------------------------------------------------------------------
// Mixed step: norm(chunk) and mu(chunk+1) interleaved 8:5 by blockIdx so the
// HW work distributor mixes DRAM-writers and DRAM-readers in every wave.
// ---------------------------------------------------------------------------
__global__ __launch_bounds__(THREADS, 2)
void step_kernel(const float* __restrict__ x, float* __restrict__ out,
                 int chunk) {
    const int grp = blockIdx.x / GRP_SZ;
    const int pos = blockIdx.x - grp * GRP_SZ;
    if (pos < GRP_NORM) {
        norm_body(x, out, chunk, grp * GRP_NORM + pos);
    } else {
        const int job = grp * GRP_MU + (pos - GRP_NORM);
        if (job < MU_JOBS) mu_body(x, chunk + 1, job);
    }
}

// Standalone mu (for chunk 0) and norm (for the last chunk).
__global__ __launch_bounds__(THREADS, 2)
void mu_kernel(const float* __restrict__ x, int chunk) {
    if (blockIdx.x < MU_JOBS) mu_body(x, chunk, blockIdx.x);
}

__global__ __launch_bounds__(THREADS, 2)
void norm_kernel(const float* __restrict__ x, float* __restrict__ out,
                 int chunk) {
    norm_body(x, out, chunk, blockIdx.x);
}

extern "C" void kernel_launch(void* const* d_in, const int* in_sizes, int n_in,
                              void* d_out, int out_size) {
    (void)in_sizes; (void)n_in; (void)out_size;
    const float* x   = (const float*)d_in[0];
    float*       out = (float*)d_out;

    mu_kernel<<<MU_JOBS, THREADS>>>(x, 0);
    for (int k = 0; k < NCHUNK - 1; ++k)
        step_kernel<<<STEP_GRID, THREADS>>>(x, out, k);
    norm_kernel<<<CHUNK_ROWS, THREADS>>>(x, out, NCHUNK - 1);
}

// round 17
// speedup vs baseline: 1.0907x; 1.0907x over previous
#include <cuda_runtime.h>

// x: (B=64, C=128, T=10000) float32, row-major.
#define B_DIM 64
#define C_DIM 128
#define T_DIM 10000
#define T4    2500              // float4 per (b,c) row
#define K2_THREADS 512
#define K2_ITERS   5            // ceil(2500/512)

// K1 geometry: 8-way channel split.
#define K1_THREADS 256
#define K1_QPC  32              // quads per CTA
#define K1_GPC  8               // channel groups per CTA
#define K1_CPG  16              // channels per group (8*16 = 128)
#define K1_GRID ((B_DIM * T4) / K1_QPC)   // 160000/32 = 5000

// Batches >= this are loaded evict-normal in K1 so they stay L2-resident for
// the reversed K2. 20 batches * 5.12MB = 102MB residue (+2.6MB mu) vs 126MB L2.
#define K1_KEEP_B 44

// Per-(batch,time) channel means: 64*10000 floats = 2.56 MB (lives in L2 for K2).
__device__ float g_mu[B_DIM * T_DIM];

// ---------------------------------------------------------------------------
// K1: mu[b,t] = mean over channels, 8-way channel split.
// Hybrid cache policy: __ldcs (evict-first) for the bulk (b < KEEP_B) so K1
// keeps full streaming speed; default (evict-normal) for the last batches so
// that data survives in L2 for the reversed K2 to hit.
// Lanes 0-31 = consecutive quads -> 512B coalesced warp reads per channel.
// ---------------------------------------------------------------------------
__global__ __launch_bounds__(K1_THREADS)
void mu_kernel(const float* __restrict__ x) {
    __shared__ float4 part[K1_GPC][K1_QPC];     // 4 KB

    const int ql = threadIdx.x & (K1_QPC - 1);
    const int g  = threadIdx.x >> 5;            // channel group 0..7
    const int q  = blockIdx.x * K1_QPC + ql;    // global quad id (ascending b)
    const int b  = q / T4;
    const int i4 = q - b * T4;

    const float4* __restrict__ xp =
        reinterpret_cast<const float4*>(x)
        + ((size_t)b * C_DIM + (size_t)g * K1_CPG) * T4 + i4;

    float sx = 0.f, sy = 0.f, sz = 0.f, sw = 0.f;
    if (b < K1_KEEP_B) {
#pragma unroll
        for (int c = 0; c < K1_CPG; ++c) {
            float4 v = __ldcs(xp + (size_t)c * T4);   // streamed, evict-first
            sx += v.x; sy += v.y; sz += v.z; sw += v.w;
        }
    } else {
#pragma unroll
        for (int c = 0; c < K1_CPG; ++c) {
            float4 v = xp[(size_t)c * T4];            // keep resident for K2
            sx += v.x; sy += v.y; sz += v.z; sw += v.w;
        }
    }
    float4 p; p.x = sx; p.y = sy; p.z = sz; p.w = sw;
    part[g][ql] = p;
    __syncthreads();

    if (threadIdx.x < K1_QPC) {
        float4 a = part[0][ql];
#pragma unroll
        for (int gg = 1; gg < K1_GPC; ++gg) {
            float4 t = part[gg][ql];
            a.x += t.x; a.y += t.y; a.z += t.z; a.w += t.w;
        }
        const float inv = 1.0f / (float)C_DIM;
        a.x *= inv; a.y *= inv; a.z *= inv; a.w *= inv;
        reinterpret_cast<float4*>(g_mu)[(size_t)b * T4 + i4] = a;
    }
}

// ---------------------------------------------------------------------------
// K2: one CTA per (b,c) row, processed in REVERSE row order so the first
// waves read the x batches K1 deliberately left in L2 (L2 persists across
// launches; only L1 flushes). d = x - mu held in registers across the block
// reduction. x via __ldcs (policy irrelevant on hits, demotes after use),
// out via __stcs (evict-first: the write stream self-evicts instead of
// displacing the x residue).
// ---------------------------------------------------------------------------
__global__ __launch_bounds__(K2_THREADS, 2)
void norm_kernel(const float* __restrict__ x, float* __restrict__ out) {
    __shared__ float red_s[16], red_s2[16];
    __shared__ float s_mean, s_inv;

    const int row = (B_DIM * C_DIM - 1) - blockIdx.x;   // reversed
    const int b   = row >> 7;

    const float4* __restrict__ xp =
        reinterpret_cast<const float4*>(x) + (size_t)row * T4;
    const float4* __restrict__ mp =
        reinterpret_cast<const float4*>(g_mu) + (size_t)b * T4;

    float4 xv[K2_ITERS], mv[K2_ITERS];
#pragma unroll
    for (int k = 0; k < K2_ITERS; ++k) {
        const int i = threadIdx.x + k * K2_THREADS;
        if (i < T4) {
            xv[k] = __ldcs(xp + i);
            mv[k] = mp[i];
        }
    }

    float s = 0.f, s2 = 0.f;
#pragma unroll
    for (int k = 0; k < K2_ITERS; ++k) {
        const int i = threadIdx.x + k * K2_THREADS;
        if (i < T4) {
            xv[k].x -= mv[k].x; xv[k].y -= mv[k].y;
            xv[k].z -= mv[k].z; xv[k].w -= mv[k].w;
            s  += xv[k].x + xv[k].y + xv[k].z + xv[k].w;
            s2 += xv[k].x * xv[k].x + xv[k].y * xv[k].y
                + xv[k].z * xv[k].z + xv[k].w * xv[k].w;
        }
    }

#pragma unroll
    for (int o = 16; o > 0; o >>= 1) {
        s  += __shfl_down_sync(0xffffffffu, s,  o);
        s2 += __shfl_down_sync(0xffffffffu, s2, o);
    }
    const int wid = threadIdx.x >> 5;
    const int lid = threadIdx.x & 31;
    if (lid == 0) { red_s[wid] = s; red_s2[wid] = s2; }
    __syncthreads();

    if (threadIdx.x < 32) {
        float a  = (lid < 16) ? red_s[lid]  : 0.f;
        float a2 = (lid < 16) ? red_s2[lid] : 0.f;
#pragma unroll
        for (int o = 8; o > 0; o >>= 1) {
            a  += __shfl_down_sync(0xffffffffu, a,  o);
            a2 += __shfl_down_sync(0xffffffffu, a2, o);
        }
        if (lid == 0) {
            const float invT = 1.0f / (float)T_DIM;
            float mean = a * invT;
            float var  = a2 * invT - mean * mean;
            float sd   = sqrtf(fmaxf(var, 0.0f));
            if (sd == 0.0f) sd = 1.0f;
            s_mean = mean;
            s_inv  = 1.0f / sd;
        }
    }
    __syncthreads();

    const float mean = s_mean;
    const float invs = s_inv;
    float4* __restrict__ op = reinterpret_cast<float4*>(out) + (size_t)row * T4;
#pragma unroll
    for (int k = 0; k < K2_ITERS; ++k) {
        const int i = threadIdx.x + k * K2_THREADS;
        if (i < T4) {
            float4 r;
            r.x = (xv[k].x - mean) * invs;
            r.y = (xv[k].y - mean) * invs;
            r.z = (xv[k].z - mean) * invs;
            r.w = (xv[k].w - mean) * invs;
            __stcs(op + i, r);
        }
    }
}

extern "C" void kernel_launch(void* const* d_in, const int* in_sizes, int n_in,
                              void* d_out, int out_size) {
    (void)in_sizes; (void)n_in; (void)out_size;
    const float* x   = (const float*)d_in[0];
    float*       out = (float*)d_out;

    mu_kernel<<<K1_GRID, K1_THREADS>>>(x);
    norm_kernel<<<B_DIM * C_DIM, K2_THREADS>>>(x, out);
}